// round 1
// baseline (speedup 1.0000x reference)
#include <cuda_runtime.h>

// LPC -> PARCOR (downward Levinson), clip, PARCOR -> LPC (upward Levinson).
// One thread per row of 25 floats. Element 0 (gain K) passes through.
// In-place trick: downward stage m only modifies c[i], i < m-1, leaving
// c[m-1] = k_m untouched forever after -> after the downward pass c[] holds
// the reflection coefficients [k_1..k_24]. The upward pass also runs in place.

#define M 24
#define ROWS_PER_BLK 128
#define SMEM_STRIDE 27   // 25 cols padded to 27 (gcd(27,32)=1 -> no bank conflicts)

__global__ __launch_bounds__(ROWS_PER_BLK)
void lpc_stability_kernel(const float* __restrict__ in, float* __restrict__ out, int B)
{
    __shared__ float s[ROWS_PER_BLK * SMEM_STRIDE];

    const int tid   = threadIdx.x;
    const int rbase = blockIdx.x * ROWS_PER_BLK;          // first row of this block
    const long long gbase = (long long)rbase * 25;        // first element of this block
    const int nvalid_rows  = min(ROWS_PER_BLK, B - rbase);
    const int nvalid_elems = nvalid_rows * 25;

    // ---- coalesced load: global -> smem (de-strided) ----
    for (int idx = tid; idx < nvalid_elems; idx += ROWS_PER_BLK) {
        int r = idx / 25;
        int c = idx - r * 25;
        s[r * SMEM_STRIDE + c] = in[gbase + idx];
    }
    __syncthreads();

    if (tid < nvalid_rows) {
        float* row = &s[tid * SMEM_STRIDE];
        float K = row[0];
        float c[M];
        #pragma unroll
        for (int i = 0; i < M; ++i) c[i] = row[i + 1];

        // ---- downward: LPC -> reflection coefficients (in place) ----
        #pragma unroll
        for (int m = M; m >= 2; --m) {
            float k   = c[m - 1];
            float inv = __fdividef(1.0f, 1.0f - k * k);
            #pragma unroll
            for (int i = 0; 2 * i <= m - 2; ++i) {
                int j = m - 2 - i;
                float ci = c[i];
                float cj = c[j];
                if (i < j) {
                    c[i] = (ci - k * cj) * inv;
                    c[j] = (cj - k * ci) * inv;
                } else {
                    c[i] = (ci - k * ci) * inv;
                }
            }
        }
        // now c[i] == k_{i+1}

        // ---- clip (BOUND = 1 - 1e-16 rounds to 1.0f in fp32) ----
        const float BOUNDF = (float)(1.0 - 1e-16);
        #pragma unroll
        for (int i = 0; i < M; ++i)
            c[i] = fminf(fmaxf(c[i], -BOUNDF), BOUNDF);

        // ---- upward: reflection coefficients -> LPC (in place) ----
        // stage m: km = c[m-1]; c[i] += km * c_old[m-2-i] for i < m-1
        #pragma unroll
        for (int m = 2; m <= M; ++m) {
            float km = c[m - 1];
            #pragma unroll
            for (int i = 0; 2 * i <= m - 2; ++i) {
                int j = m - 2 - i;
                float ci = c[i];
                float cj = c[j];
                if (i < j) {
                    c[i] = ci + km * cj;
                    c[j] = cj + km * ci;
                } else {
                    c[i] = ci + km * ci;
                }
            }
        }

        row[0] = K;
        #pragma unroll
        for (int i = 0; i < M; ++i) row[i + 1] = c[i];
    }
    __syncthreads();

    // ---- coalesced store: smem -> global ----
    for (int idx = tid; idx < nvalid_elems; idx += ROWS_PER_BLK) {
        int r = idx / 25;
        int c = idx - r * 25;
        out[gbase + idx] = s[r * SMEM_STRIDE + c];
    }
}

extern "C" void kernel_launch(void* const* d_in, const int* in_sizes, int n_in,
                              void* d_out, int out_size)
{
    const float* a = (const float*)d_in[0];
    float* out = (float*)d_out;
    int B = in_sizes[0] / 25;
    int grid = (B + ROWS_PER_BLK - 1) / ROWS_PER_BLK;
    lpc_stability_kernel<<<grid, ROWS_PER_BLK>>>(a, out, B);
}

// round 2
// speedup vs baseline: 1.5036x; 1.5036x over previous
#include <cuda_runtime.h>

// LPC -> PARCOR (downward Levinson), clip at ±1.0f (== 1-1e-16 in fp32),
// PARCOR -> LPC (upward). Key identity: if NO reflection coefficient clips,
// the round trip is the identity, so the output row == the input row (the
// reference's own fp32 round-trip noise is ~1e-7, far under the 1e-3 gate).
// So: compute only the downward recursion to get the k's; if max|k| <= 1,
// leave the original row (still in smem) untouched. Only clipped rows (rare
// to nonexistent for this data) pay for clamp + upward recursion.
//
// smem layout is UNPADDED stride-25: gcd(25,32)=1 makes per-thread row reads
// bank-conflict-free, and staging becomes a plain contiguous float4 memcpy.

#define M 24
#define ROW 25
#define ROWS_PER_BLK 128
#define ELEMS (ROWS_PER_BLK * ROW)   // 3200 floats per block
#define VECS  (ELEMS / 4)            // 800 float4 per block

__global__ __launch_bounds__(ROWS_PER_BLK)
void lpc_stability_kernel(const float* __restrict__ in, float* __restrict__ out, int B)
{
    __shared__ float s[ELEMS];

    const int tid   = threadIdx.x;
    const int rbase = blockIdx.x * ROWS_PER_BLK;
    const long long gbase = (long long)blockIdx.x * ELEMS;
    const int nrows = min(ROWS_PER_BLK, B - rbase);
    const bool full = (nrows == ROWS_PER_BLK);

    // ---- staging in: contiguous vectorized copy (full blocks) ----
    if (full) {
        const float4* __restrict__ g4 = (const float4*)(in + gbase);
        float4* s4 = (float4*)s;
        #pragma unroll
        for (int i = 0; i < 7; ++i) {
            int idx = tid + i * ROWS_PER_BLK;
            if (idx < VECS) s4[idx] = g4[idx];
        }
    } else {
        int nelems = nrows * ROW;
        for (int idx = tid; idx < nelems; idx += ROWS_PER_BLK)
            s[idx] = in[gbase + idx];
    }
    __syncthreads();

    if (tid < nrows) {
        float* row = &s[tid * ROW];
        float c[M];
        #pragma unroll
        for (int i = 0; i < M; ++i) c[i] = row[i + 1];

        // ---- downward: LPC -> reflection coefficients (in place) ----
        float maxa = 0.0f;
        #pragma unroll
        for (int m = M; m >= 2; --m) {
            float k = c[m - 1];
            maxa = fmaxf(maxa, fabsf(k));
            float inv = __fdividef(1.0f, 1.0f - k * k);
            #pragma unroll
            for (int i = 0; 2 * i <= m - 2; ++i) {
                int j = m - 2 - i;
                float ci = c[i];
                float cj = c[j];
                if (i < j) {
                    c[i] = fmaf(-k, cj, ci) * inv;
                    c[j] = fmaf(-k, ci, cj) * inv;
                } else {
                    c[i] = fmaf(-k, ci, ci) * inv;
                }
            }
        }
        maxa = fmaxf(maxa, fabsf(c[0]));   // k_1

        // ---- rare path: some |k| > 1 -> clamp + upward, write back ----
        if (maxa > 1.0f) {
            #pragma unroll
            for (int i = 0; i < M; ++i)
                c[i] = fminf(fmaxf(c[i], -1.0f), 1.0f);

            #pragma unroll
            for (int m = 2; m <= M; ++m) {
                float km = c[m - 1];
                #pragma unroll
                for (int i = 0; 2 * i <= m - 2; ++i) {
                    int j = m - 2 - i;
                    float ci = c[i];
                    float cj = c[j];
                    if (i < j) {
                        c[i] = fmaf(km, cj, ci);
                        c[j] = fmaf(km, ci, cj);
                    } else {
                        c[i] = fmaf(km, ci, ci);
                    }
                }
            }
            #pragma unroll
            for (int i = 0; i < M; ++i) row[i + 1] = c[i];
            // row[0] (gain K) untouched in smem
        }
        // common path: no clip -> round trip is identity; smem row already
        // holds the answer (the original input row).
    }
    __syncthreads();

    // ---- staging out: contiguous vectorized copy ----
    if (full) {
        const float4* s4 = (const float4*)s;
        float4* __restrict__ o4 = (float4*)(out + gbase);
        #pragma unroll
        for (int i = 0; i < 7; ++i) {
            int idx = tid + i * ROWS_PER_BLK;
            if (idx < VECS) o4[idx] = s4[idx];
        }
    } else {
        int nelems = nrows * ROW;
        for (int idx = tid; idx < nelems; idx += ROWS_PER_BLK)
            out[gbase + idx] = s[idx];
    }
}

extern "C" void kernel_launch(void* const* d_in, const int* in_sizes, int n_in,
                              void* d_out, int out_size)
{
    const float* a = (const float*)d_in[0];
    float* out = (float*)d_out;
    int B = in_sizes[0] / ROW;
    int grid = (B + ROWS_PER_BLK - 1) / ROWS_PER_BLK;
    lpc_stability_kernel<<<grid, ROWS_PER_BLK>>>(a, out, B);
}

// round 3
// speedup vs baseline: 1.5437x; 1.0266x over previous
#include <cuda_runtime.h>

// LPC -> PARCOR (downward Levinson) to detect clipping; clip at ±1.0f
// (== 1-1e-16 in fp32); if nothing clips (the overwhelmingly common case),
// the PARCOR->LPC round trip is the identity, so out == in.
//
// This version DECOUPLES the HBM stream from the compute: every thread
// loads its float4 slices and stores them to `out` immediately (pure
// streaming copy), while the Levinson recursion runs on the smem-staged
// copy purely as a clip *detector*. Only clipped rows (rare to nonexistent)
// run the upward recursion and overwrite their row with scalar stores,
// after a barrier that orders them behind the bulk store.

#define M 24
#define ROW 25
#define ROWS_PER_BLK 256
#define ELEMS (ROWS_PER_BLK * ROW)   // 6400 floats per block
#define VECS  (ELEMS / 4)            // 1600 float4 per block

__global__ __launch_bounds__(ROWS_PER_BLK)
void lpc_stability_kernel(const float* __restrict__ in, float* __restrict__ out, int B)
{
    __shared__ float s[ELEMS];

    const int tid   = threadIdx.x;
    const int rbase = blockIdx.x * ROWS_PER_BLK;
    const long long gbase = (long long)blockIdx.x * ELEMS;
    const int nrows = min(ROWS_PER_BLK, B - rbase);

    if (nrows == ROWS_PER_BLK) {
        // ---- streaming copy + smem stage, fully vectorized ----
        const float4* __restrict__ g4 = (const float4*)(in + gbase);
        float4* __restrict__ o4 = (float4*)(out + gbase);
        float4* s4 = (float4*)s;
        #pragma unroll
        for (int i = 0; i < 7; ++i) {
            int idx = tid + i * ROWS_PER_BLK;
            if (idx < VECS) {
                float4 v = g4[idx];
                o4[idx] = v;      // output committed immediately (common path)
                s4[idx] = v;      // staged for the clip detector
            }
        }
    } else {
        int nelems = nrows * ROW;
        for (int idx = tid; idx < nelems; idx += ROWS_PER_BLK) {
            float v = in[gbase + idx];
            out[gbase + idx] = v;
            s[idx] = v;
        }
    }
    __syncthreads();   // orders bulk stores before any fixup store; smem ready

    if (tid < nrows) {
        const float* row = &s[tid * ROW];
        float c[M];
        #pragma unroll
        for (int i = 0; i < M; ++i) c[i] = row[i + 1];

        // ---- downward: LPC -> reflection coefficients (in place) ----
        float maxa = 0.0f;
        #pragma unroll
        for (int m = M; m >= 2; --m) {
            float k = c[m - 1];
            maxa = fmaxf(maxa, fabsf(k));
            float inv = __fdividef(1.0f, 1.0f - k * k);
            #pragma unroll
            for (int i = 0; 2 * i <= m - 2; ++i) {
                int j = m - 2 - i;
                float ci = c[i];
                float cj = c[j];
                if (i < j) {
                    c[i] = fmaf(-k, cj, ci) * inv;
                    c[j] = fmaf(-k, ci, cj) * inv;
                } else {
                    c[i] = fmaf(-k, ci, ci) * inv;
                }
            }
        }
        maxa = fmaxf(maxa, fabsf(c[0]));   // k_1

        // ---- rare path: clamp + upward recursion, overwrite this row ----
        if (maxa > 1.0f) {
            #pragma unroll
            for (int i = 0; i < M; ++i)
                c[i] = fminf(fmaxf(c[i], -1.0f), 1.0f);

            #pragma unroll
            for (int m = 2; m <= M; ++m) {
                float km = c[m - 1];
                #pragma unroll
                for (int i = 0; 2 * i <= m - 2; ++i) {
                    int j = m - 2 - i;
                    float ci = c[i];
                    float cj = c[j];
                    if (i < j) {
                        c[i] = fmaf(km, cj, ci);
                        c[j] = fmaf(km, ci, cj);
                    } else {
                        c[i] = fmaf(km, ci, ci);
                    }
                }
            }
            float* orow = out + gbase + (long long)tid * ROW;
            #pragma unroll
            for (int i = 0; i < M; ++i) orow[i + 1] = c[i];
            // orow[0] (gain K) already correct from the bulk copy
        }
    }
}

extern "C" void kernel_launch(void* const* d_in, const int* in_sizes, int n_in,
                              void* d_out, int out_size)
{
    const float* a = (const float*)d_in[0];
    float* out = (float*)d_out;
    int B = in_sizes[0] / ROW;
    int grid = (B + ROWS_PER_BLK - 1) / ROWS_PER_BLK;
    lpc_stability_kernel<<<grid, ROWS_PER_BLK>>>(a, out, B);
}

// round 4
// speedup vs baseline: 1.6193x; 1.0490x over previous
#include <cuda_runtime.h>

// LPC -> PARCOR downward Levinson as a CLIP DETECTOR, division-free:
// track u_i = c_i * D with running denominator D = prod(1 - k^2).
//   k    = u[m-1] / D
//   D'   = D - k*u[m-1]          ( = D*(1-k^2) )
//   u'_i = u_i - k*u_j           ( = c'_i * D'  )
// One FMA per element instead of FMA+MUL -> half the fma-pipe work.
// If no |k| > 1 (common case; BOUND=1-1e-16 rounds to 1.0f), the
// PARCOR->LPC round trip is the identity and out == in, already streamed.
// Clipped / degenerate rows (incl. D underflow -> k=inf) take the exact
// textbook path: unscaled downward recursion + clamp + upward recursion.

#define M 24
#define ROW 25
#define ROWS_PER_BLK 256
#define ELEMS (ROWS_PER_BLK * ROW)   // 6400 floats per block
#define VECS  (ELEMS / 4)            // 1600 float4 per block

__global__ __launch_bounds__(ROWS_PER_BLK)
void lpc_stability_kernel(const float* __restrict__ in, float* __restrict__ out, int B)
{
    __shared__ float s[ELEMS];

    const int tid   = threadIdx.x;
    const int rbase = blockIdx.x * ROWS_PER_BLK;
    const long long gbase = (long long)blockIdx.x * ELEMS;
    const int nrows = min(ROWS_PER_BLK, B - rbase);

    if (nrows == ROWS_PER_BLK) {
        const float4* __restrict__ g4 = (const float4*)(in + gbase);
        float4* __restrict__ o4 = (float4*)(out + gbase);
        float4* s4 = (float4*)s;
        #pragma unroll
        for (int i = 0; i < 7; ++i) {
            int idx = tid + i * ROWS_PER_BLK;
            if (idx < VECS) {
                float4 v = g4[idx];
                o4[idx] = v;      // commit output immediately (common path)
                s4[idx] = v;      // stage for the detector
            }
        }
    } else {
        int nelems = nrows * ROW;
        for (int idx = tid; idx < nelems; idx += ROWS_PER_BLK) {
            float v = in[gbase + idx];
            out[gbase + idx] = v;
            s[idx] = v;
        }
    }
    __syncthreads();   // orders bulk stores before fixup stores; smem ready

    if (tid < nrows) {
        const float* row = &s[tid * ROW];
        float u[M];
        #pragma unroll
        for (int i = 0; i < M; ++i) u[i] = row[i + 1];

        // ---- scaled downward recursion (detector) ----
        float D = 1.0f;
        float maxa = 0.0f;
        #pragma unroll
        for (int m = M; m >= 2; --m) {
            float um = u[m - 1];
            float k  = um * __fdividef(1.0f, D);
            maxa = fmaxf(maxa, fabsf(k));
            D = fmaf(-k, um, D);                 // D *= (1 - k^2)
            #pragma unroll
            for (int i = 0; 2 * i <= m - 2; ++i) {
                int j = m - 2 - i;
                float ui = u[i];
                float uj = u[j];
                if (i < j) {
                    u[i] = fmaf(-k, uj, ui);
                    u[j] = fmaf(-k, ui, uj);
                } else {
                    u[i] = fmaf(-k, ui, ui);
                }
            }
        }
        // k_1 = u[0]/D
        maxa = fmaxf(maxa, fabsf(u[0] * __fdividef(1.0f, D)));

        // ---- rare path: exact recursion with clamp + reconstruction ----
        if (!(maxa <= 1.0f)) {   // catches >1 and NaN (degenerate D)
            float c[M];
            #pragma unroll
            for (int i = 0; i < M; ++i) c[i] = row[i + 1];

            #pragma unroll
            for (int m = M; m >= 2; --m) {
                float k   = c[m - 1];
                float inv = __fdividef(1.0f, 1.0f - k * k);
                #pragma unroll
                for (int i = 0; 2 * i <= m - 2; ++i) {
                    int j = m - 2 - i;
                    float ci = c[i];
                    float cj = c[j];
                    if (i < j) {
                        c[i] = fmaf(-k, cj, ci) * inv;
                        c[j] = fmaf(-k, ci, cj) * inv;
                    } else {
                        c[i] = fmaf(-k, ci, ci) * inv;
                    }
                }
            }
            #pragma unroll
            for (int i = 0; i < M; ++i)
                c[i] = fminf(fmaxf(c[i], -1.0f), 1.0f);

            #pragma unroll
            for (int m = 2; m <= M; ++m) {
                float km = c[m - 1];
                #pragma unroll
                for (int i = 0; 2 * i <= m - 2; ++i) {
                    int j = m - 2 - i;
                    float ci = c[i];
                    float cj = c[j];
                    if (i < j) {
                        c[i] = fmaf(km, cj, ci);
                        c[j] = fmaf(km, ci, cj);
                    } else {
                        c[i] = fmaf(km, ci, ci);
                    }
                }
            }
            float* orow = out + gbase + (long long)tid * ROW;
            #pragma unroll
            for (int i = 0; i < M; ++i) orow[i + 1] = c[i];
            // orow[0] (gain K) already correct from the bulk copy
        }
    }
}

extern "C" void kernel_launch(void* const* d_in, const int* in_sizes, int n_in,
                              void* d_out, int out_size)
{
    const float* a = (const float*)d_in[0];
    float* out = (float*)d_out;
    int B = in_sizes[0] / ROW;
    int grid = (B + ROWS_PER_BLK - 1) / ROWS_PER_BLK;
    lpc_stability_kernel<<<grid, ROWS_PER_BLK>>>(a, out, B);
}